// round 4
// baseline (speedup 1.0000x reference)
#include <cuda_runtime.h>

// ---------------- problem constants (fixed shapes for this problem) ----------
#define MAXN   300000
#define NV0    60000
#define NV1    30000
#define NV2    15000
#define NV3    120000
#define NVIN   105000     // NV0+NV1+NV2
#define NVTOT  225000     // + NV3
#define VB0    0
#define VB1    60000
#define VB2    90000
#define VB3    105000
#define CH_OUT 128
#define HW     512

// ---------------- device scratch (static: no runtime allocation) -------------
__device__ int   g_cnt[NVTOT];
__device__ int   g_off[NVTOT];
__device__ int   g_cur[NVTOT];
__device__ int   g_pidx[4 * MAXN];
__device__ float g_sfcat[(size_t)MAXN * 192];   // [n][s*64+c] concatenated sf
__device__ float g_vmax1[(size_t)NVIN * 64];    // per input voxel max
__device__ float g_U[(size_t)NVIN * 128];       // vmax1 @ W_pt2_oddblock
__device__ float g_pmean3[NV3 * 4];             // output-scale voxel means
__device__ float g_sf2[(size_t)MAXN * 128];     // AVFEO per-point sf
__device__ float g_vmax2[(size_t)NV3 * 128];    // output-scale voxel max

__constant__ int c_vbase[4] = {VB0, VB1, VB2, VB3};

// ---------------- K0: zero counters ------------------------------------------
__global__ void k_zero_cnt() {
    int i = blockIdx.x * blockDim.x + threadIdx.x;
    if (i < NVTOT) g_cnt[i] = 0;
}

// ---------------- K1: per-voxel counts (all 4 scales) -------------------------
__global__ void k_count(const int* __restrict__ bev, int N) {
    int n = blockIdx.x * blockDim.x + threadIdx.x;
    if (n >= N) return;
#pragma unroll
    for (int s = 0; s < 4; s++) {
        int v = bev[s * N + n];
        atomicAdd(&g_cnt[c_vbase[s] + v], 1);
    }
}

// ---------------- K2: exclusive scan per scale (one block per scale) ----------
__global__ void k_scan() {
    int s = blockIdx.x;
    int V = (s == 0) ? NV0 : (s == 1) ? NV1 : (s == 2) ? NV2 : NV3;
    int base = c_vbase[s];
    int t = threadIdx.x;
    int chunk = (V + 1023) >> 10;
    int st = t * chunk;
    int en = st + chunk; if (en > V) en = V;
    int sum = 0;
    for (int i = st; i < en; i++) sum += g_cnt[base + i];
    __shared__ int sh[1024];
    sh[t] = sum;
    __syncthreads();
    for (int d = 1; d < 1024; d <<= 1) {
        int v = (t >= d) ? sh[t - d] : 0;
        __syncthreads();
        sh[t] += v;
        __syncthreads();
    }
    int run = sh[t] - sum;   // exclusive prefix
    for (int i = st; i < en; i++) {
        int c = g_cnt[base + i];
        g_off[base + i] = run;
        g_cur[base + i] = run;
        run += c;
    }
}

// ---------------- K3: fill CSR point lists ------------------------------------
__global__ void k_fill(const int* __restrict__ bev, int N) {
    int n = blockIdx.x * blockDim.x + threadIdx.x;
    if (n >= N) return;
#pragma unroll
    for (int s = 0; s < 4; s++) {
        int v = bev[s * N + n];
        int pos = atomicAdd(&g_cur[c_vbase[s] + v], 1);
        g_pidx[s * N + pos] = n;
    }
}

// ---------------- K4: AVFE voxel-major (scales 0..2) + means for scale 3 ------
// one warp per voxel slot; lanes cover 2 channels each (c, c+32)
__global__ void __launch_bounds__(256) k_avfe(
    const float4* __restrict__ pts,
    const float* __restrict__ Wpt1,    // [4][64]
    const float* __restrict__ Watt1,   // [8][64]
    int N)
{
    __shared__ float sW1[256];
    __shared__ float sA1[512];
    int t = threadIdx.x;
    sW1[t] = Wpt1[t];
    sA1[t] = Watt1[t];
    sA1[t + 256] = Watt1[t + 256];
    __syncthreads();

    int gv = blockIdx.x * 8 + (t >> 5);
    int lane = t & 31;
    if (gv >= NVTOT) return;

    int s;
    if (gv < VB1) s = 0;
    else if (gv < VB2) s = 1;
    else if (gv < VB3) s = 2;
    else s = 3;

    int off = g_off[gv];
    int cnt = g_cnt[gv];
    const int* pix = &g_pidx[s * N + off];

    // ---- voxel mean ----
    float sx = 0.f, sy = 0.f, sz = 0.f, sw = 0.f;
    for (int j = lane; j < cnt; j += 32) {
        float4 p = pts[pix[j]];
        sx += p.x; sy += p.y; sz += p.z; sw += p.w;
    }
#pragma unroll
    for (int d = 16; d > 0; d >>= 1) {
        sx += __shfl_xor_sync(0xffffffffu, sx, d);
        sy += __shfl_xor_sync(0xffffffffu, sy, d);
        sz += __shfl_xor_sync(0xffffffffu, sz, d);
        sw += __shfl_xor_sync(0xffffffffu, sw, d);
    }
    float inv = 1.0f / fmaxf((float)cnt, 1.0f);
    float mx = sx * inv, my = sy * inv, mz = sz * inv, mw = sw * inv;

    if (s == 3) {
        if (lane == 0) {
            ((float4*)g_pmean3)[gv - VB3] = make_float4(mx, my, mz, mw);
        }
        return;
    }

    int cA = lane, cB = lane + 32;
    float mA = 0.f, mB = 0.f;
    for (int j = 0; j < cnt; j++) {
        int n = pix[j];             // broadcast load
        float4 p = pts[n];
        float a0 = p.x - mx, a1 = p.y - my, a2 = p.z - mz, a3 = p.w;
        // pf1 = relu(p @ W_pt1)
        float pfA = p.x * sW1[cA] + p.y * sW1[64 + cA] + p.z * sW1[128 + cA] + p.w * sW1[192 + cA];
        float pfB = p.x * sW1[cB] + p.y * sW1[64 + cB] + p.z * sW1[128 + cB] + p.w * sW1[192 + cB];
        pfA = fmaxf(pfA, 0.f); pfB = fmaxf(pfB, 0.f);
        // af = relu(att @ W_att1), att = [dx,dy,dz,p3, mx,my,mz,mw]
        float afA = a0 * sA1[cA] + a1 * sA1[64 + cA] + a2 * sA1[128 + cA] + a3 * sA1[192 + cA]
                  + mx * sA1[256 + cA] + my * sA1[320 + cA] + mz * sA1[384 + cA] + mw * sA1[448 + cA];
        float afB = a0 * sA1[cB] + a1 * sA1[64 + cB] + a2 * sA1[128 + cB] + a3 * sA1[192 + cB]
                  + mx * sA1[256 + cB] + my * sA1[320 + cB] + mz * sA1[384 + cB] + mw * sA1[448 + cB];
        afA = fmaxf(afA, 0.f); afB = fmaxf(afB, 0.f);
        float fA = pfA * afA, fB = pfB * afB;
        mA = fmaxf(mA, fA); mB = fmaxf(mB, fB);
        float* dst = &g_sfcat[(size_t)n * 192 + s * 64];
        dst[cA] = fA;
        dst[cB] = fB;
    }
    float* vdst = &g_vmax1[(size_t)gv * 64];
    vdst[cA] = mA;
    vdst[cB] = mB;
}

// ---------------- K5: U = vmax1 @ W_pt2[odd block]  (per input voxel) ---------
__global__ void k_umm(const float* __restrict__ Wpt2) {
    int gv = blockIdx.x;
    int t = threadIdx.x;     // output channel 0..127
    int s = (gv < VB1) ? 0 : (gv < VB2) ? 1 : 2;
    __shared__ float vr[64];
    if (t < 64) vr[t] = g_vmax1[(size_t)gv * 64 + t];
    __syncthreads();
    const float* Wp = Wpt2 + (size_t)(128 * s + 64) * 128 + t;  // rows 128s+64 ..
    float acc = 0.f;
#pragma unroll 16
    for (int k = 0; k < 64; k++) acc = fmaf(vr[k], Wp[(size_t)k * 128], acc);
    g_U[(size_t)gv * 128 + t] = acc;
}

// ---------------- K6a: big matvec + AVFEO attention, point-major --------------
// block = 512 thr (16 warps), warp handles 4 points, lane handles 4 channels
#define AVFEO_SMEM ((24576 + 1024 + 16 * 768) * 4)
__global__ void __launch_bounds__(512, 1) k_avfeo(
    const float4* __restrict__ pts,
    const float* __restrict__ Wpt2,    // [384][128]
    const float* __restrict__ Watt2,   // [8][128]
    const int* __restrict__ bev,
    int N)
{
    extern __shared__ float smem[];
    float* sWe = smem;                // [192][128] even blocks of W_pt2
    float* sA2 = smem + 24576;        // [8][128]
    float* sXS = smem + 24576 + 1024; // [16 warps][4 pts][192]
    int t = threadIdx.x;

    // stage even-block weights: sWe[s*64+k][c] = Wpt2[128s+k][c]
    for (int i = t; i < 6144; i += 512) {        // float4 granularity
        int idx = i * 4;
        int row = idx >> 7;
        int c = idx & 127;
        int grow = ((row >> 6) * 128) + (row & 63);
        ((float4*)sWe)[i] = *(const float4*)(Wpt2 + (size_t)grow * 128 + c);
    }
    for (int i = t; i < 1024; i += 512) sA2[i] = Watt2[i];
    __syncthreads();

    int w = t >> 5, lane = t & 31;
    float* xs = sXS + w * 768;
    const float4* U4 = (const float4*)g_U;
    const float4* We4 = (const float4*)sWe;
    const float4* A4 = (const float4*)sA2;
    int NG = (N + 63) >> 6;   // groups of 64 points per block iteration

    for (int g = blockIdx.x; g < NG; g += gridDim.x) {
        int nbase = g * 64 + w * 4;

        // stage x rows (4 points x 192 floats) into shared
#pragma unroll
        for (int r = 0; r < 6; r++) {
            int fid = lane + r * 32;             // 0..191 float4 slot
            int p = fid / 48, k4 = fid % 48;
            int n = nbase + p;
            float4 v = (n < N) ? ((const float4*)g_sfcat)[(size_t)n * 48 + k4]
                               : make_float4(0.f, 0.f, 0.f, 0.f);
            ((float4*)xs)[p * 48 + k4] = v;
        }
        __syncwarp();

        // init accumulators from U gathers
        float4 acc[4];
        int i3[4];
#pragma unroll
        for (int p = 0; p < 4; p++) {
            int n = nbase + p;
            if (n < N) {
                int i0 = bev[n];
                int i1 = bev[N + n];
                int i2 = bev[2 * N + n];
                i3[p] = bev[3 * N + n];
                float4 a = U4[(size_t)i0 * 32 + lane];
                float4 b = U4[(size_t)(VB1 + i1) * 32 + lane];
                float4 c = U4[(size_t)(VB2 + i2) * 32 + lane];
                acc[p] = make_float4(a.x + b.x + c.x, a.y + b.y + c.y,
                                     a.z + b.z + c.z, a.w + b.w + c.w);
            } else {
                i3[p] = 0;
                acc[p] = make_float4(0.f, 0.f, 0.f, 0.f);
            }
        }

        // main matvec: 192 x (4 pts x 4 ch)
#pragma unroll 4
        for (int k = 0; k < 192; k++) {
            float4 wv = We4[k * 32 + lane];
            float x0 = xs[k], x1 = xs[192 + k], x2 = xs[384 + k], x3 = xs[576 + k];
            acc[0].x = fmaf(x0, wv.x, acc[0].x); acc[0].y = fmaf(x0, wv.y, acc[0].y);
            acc[0].z = fmaf(x0, wv.z, acc[0].z); acc[0].w = fmaf(x0, wv.w, acc[0].w);
            acc[1].x = fmaf(x1, wv.x, acc[1].x); acc[1].y = fmaf(x1, wv.y, acc[1].y);
            acc[1].z = fmaf(x1, wv.z, acc[1].z); acc[1].w = fmaf(x1, wv.w, acc[1].w);
            acc[2].x = fmaf(x2, wv.x, acc[2].x); acc[2].y = fmaf(x2, wv.y, acc[2].y);
            acc[2].z = fmaf(x2, wv.z, acc[2].z); acc[2].w = fmaf(x2, wv.w, acc[2].w);
            acc[3].x = fmaf(x3, wv.x, acc[3].x); acc[3].y = fmaf(x3, wv.y, acc[3].y);
            acc[3].z = fmaf(x3, wv.z, acc[3].z); acc[3].w = fmaf(x3, wv.w, acc[3].w);
        }

        // epilogue: af2 attention, relu, product, store sf2
#pragma unroll
        for (int p = 0; p < 4; p++) {
            int n = nbase + p;
            if (n >= N) continue;
            float4 pt = pts[n];
            float4 pm = ((const float4*)g_pmean3)[i3[p]];
            float att[8];
            att[0] = pt.x - pm.x; att[1] = pt.y - pm.y; att[2] = pt.z - pm.z; att[3] = pt.w;
            att[4] = pm.x; att[5] = pm.y; att[6] = pm.z; att[7] = pm.w;
            float4 af = make_float4(0.f, 0.f, 0.f, 0.f);
#pragma unroll
            for (int k = 0; k < 8; k++) {
                float4 wv = A4[k * 32 + lane];
                af.x = fmaf(att[k], wv.x, af.x);
                af.y = fmaf(att[k], wv.y, af.y);
                af.z = fmaf(att[k], wv.z, af.z);
                af.w = fmaf(att[k], wv.w, af.w);
            }
            float4 sf;
            sf.x = fmaxf(acc[p].x, 0.f) * fmaxf(af.x, 0.f);
            sf.y = fmaxf(acc[p].y, 0.f) * fmaxf(af.y, 0.f);
            sf.z = fmaxf(acc[p].z, 0.f) * fmaxf(af.z, 0.f);
            sf.w = fmaxf(acc[p].w, 0.f) * fmaxf(af.w, 0.f);
            ((float4*)g_sf2)[(size_t)n * 32 + lane] = sf;
        }
        __syncwarp();
    }
}

// ---------------- K6b: segment max over output voxels -------------------------
__global__ void k_vmax2(int N) {
    int gw = (blockIdx.x * blockDim.x + threadIdx.x) >> 5;
    int lane = threadIdx.x & 31;
    if (gw >= NV3) return;
    int off = g_off[VB3 + gw];
    int cnt = g_cnt[VB3 + gw];
    const int* pix = &g_pidx[3 * N + off];
    float4 m = make_float4(0.f, 0.f, 0.f, 0.f);
    for (int j = 0; j < cnt; j++) {
        float4 v = ((const float4*)g_sf2)[(size_t)pix[j] * 32 + lane];
        m.x = fmaxf(m.x, v.x); m.y = fmaxf(m.y, v.y);
        m.z = fmaxf(m.z, v.z); m.w = fmaxf(m.w, v.w);
    }
    ((float4*)g_vmax2)[(size_t)gw * 32 + lane] = m;
}

// ---------------- K7: scatter to dense NCHW output ----------------------------
__global__ void k_scatter(const int* __restrict__ vfs, float* __restrict__ out) {
    int t = blockIdx.x * blockDim.x + threadIdx.x;
    if (t >= NV3 * CH_OUT) return;
    int o = t >> 7, c = t & 127;
    float v = g_vmax2[t];
    int b = vfs[o * 3], y = vfs[o * 3 + 1], x = vfs[o * 3 + 2];
    out[(((size_t)b * CH_OUT + c) * HW + y) * HW + x] = v;
}

// ---------------- launch ------------------------------------------------------
extern "C" void kernel_launch(void* const* d_in, const int* in_sizes, int n_in,
                              void* d_out, int out_size) {
    const float* pts   = (const float*)d_in[0];
    const float* Wpt1  = (const float*)d_in[1];
    const float* Watt1 = (const float*)d_in[2];
    const float* Wpt2  = (const float*)d_in[3];
    const float* Watt2 = (const float*)d_in[4];
    const int*   bev   = (const int*)d_in[5];
    const int*   vfs   = (const int*)d_in[6];
    float* out = (float*)d_out;
    int N = in_sizes[0] / 4;
    if (N > MAXN) N = MAXN;

    cudaMemsetAsync(d_out, 0, (size_t)out_size * sizeof(float), 0);
    k_zero_cnt<<<(NVTOT + 255) / 256, 256>>>();
    k_count<<<(N + 255) / 256, 256>>>(bev, N);
    k_scan<<<4, 1024>>>();
    k_fill<<<(N + 255) / 256, 256>>>(bev, N);
    k_avfe<<<(NVTOT + 7) / 8, 256>>>((const float4*)pts, Wpt1, Watt1, N);
    k_umm<<<NVIN, 128>>>(Wpt2);
    cudaFuncSetAttribute(k_avfeo, cudaFuncAttributeMaxDynamicSharedMemorySize, AVFEO_SMEM);
    k_avfeo<<<592, 512, AVFEO_SMEM>>>((const float4*)pts, Wpt2, Watt2, bev, N);
    k_vmax2<<<(NV3 * 32 + 255) / 256, 256>>>(N);
    k_scatter<<<(NV3 * CH_OUT + 255) / 256, 256>>>(vfs, out);
}

// round 7
// speedup vs baseline: 1.2149x; 1.2149x over previous
#include <cuda_runtime.h>

// ---------------- problem constants (fixed shapes for this problem) ----------
#define MAXN   300000
#define NV0    60000
#define NV1    30000
#define NV2    15000
#define NV3    120000
#define NVIN   105000     // NV0+NV1+NV2
#define NVTOT  225000     // + NV3
#define VB0    0
#define VB1    60000
#define VB2    90000
#define VB3    105000
#define CH_OUT 128
#define HW     512

typedef unsigned long long u64;

// ---------------- packed f32x2 helpers (FFMA2 path, sm_103a) -----------------
__device__ __forceinline__ u64 pack2(float x) {
    u64 r; asm("mov.b64 %0, {%1, %1};" : "=l"(r) : "r"(__float_as_uint(x)));
    return r;
}
__device__ __forceinline__ u64 pack_pair(float a, float b) {
    u64 r; asm("mov.b64 %0, {%1, %2};" : "=l"(r)
               : "r"(__float_as_uint(a)), "r"(__float_as_uint(b)));
    return r;
}
__device__ __forceinline__ void fma2(u64& d, u64 a, u64 b) {
    asm("fma.rn.f32x2 %0, %1, %2, %0;" : "+l"(d) : "l"(a), "l"(b));
}
__device__ __forceinline__ float2 unpack2(u64 v) {
    float2 f; asm("mov.b64 {%0, %1}, %2;" : "=f"(f.x), "=f"(f.y) : "l"(v));
    return f;
}

// ---------------- device scratch (static: no runtime allocation) -------------
__device__ int   g_cnt[NVTOT];
__device__ int   g_off[NVTOT];
__device__ int   g_cur[NVTOT];
__device__ int   g_pidx[4 * MAXN];
__device__ float g_sfcat[(size_t)MAXN * 192];   // [n][s*64+c] concatenated sf
__device__ float g_vmax1[(size_t)NVIN * 64];    // per input voxel max
__device__ float g_U[(size_t)NVIN * 128];       // vmax1 @ W_pt2_oddblock
__device__ float g_pmean3[NV3 * 4];             // output-scale voxel means
__device__ float g_sf2[(size_t)MAXN * 128];     // AVFEO per-point sf

__constant__ int c_vbase[4] = {VB0, VB1, VB2, VB3};

// ---------------- K0: zero counters ------------------------------------------
__global__ void k_zero_cnt() {
    int i = blockIdx.x * blockDim.x + threadIdx.x;
    if (i < NVTOT) g_cnt[i] = 0;
}

// ---------------- K1: per-voxel counts (all 4 scales) -------------------------
__global__ void k_count(const int* __restrict__ bev, int N) {
    int n = blockIdx.x * blockDim.x + threadIdx.x;
    if (n >= N) return;
#pragma unroll
    for (int s = 0; s < 4; s++) {
        int v = bev[s * N + n];
        atomicAdd(&g_cnt[c_vbase[s] + v], 1);
    }
}

// ---------------- K2: exclusive scan per scale (one block per scale) ----------
__global__ void k_scan() {
    int s = blockIdx.x;
    int V = (s == 0) ? NV0 : (s == 1) ? NV1 : (s == 2) ? NV2 : NV3;
    int base = c_vbase[s];
    int t = threadIdx.x;
    int chunk = (V + 1023) >> 10;
    int st = t * chunk;
    int en = st + chunk; if (en > V) en = V;
    int sum = 0;
    for (int i = st; i < en; i++) sum += g_cnt[base + i];
    __shared__ int sh[1024];
    sh[t] = sum;
    __syncthreads();
    for (int d = 1; d < 1024; d <<= 1) {
        int v = (t >= d) ? sh[t - d] : 0;
        __syncthreads();
        sh[t] += v;
        __syncthreads();
    }
    int run = sh[t] - sum;   // exclusive prefix
    for (int i = st; i < en; i++) {
        int c = g_cnt[base + i];
        g_off[base + i] = run;
        g_cur[base + i] = run;
        run += c;
    }
}

// ---------------- K3: fill CSR point lists ------------------------------------
__global__ void k_fill(const int* __restrict__ bev, int N) {
    int n = blockIdx.x * blockDim.x + threadIdx.x;
    if (n >= N) return;
#pragma unroll
    for (int s = 0; s < 4; s++) {
        int v = bev[s * N + n];
        int pos = atomicAdd(&g_cur[c_vbase[s] + v], 1);
        g_pidx[s * N + pos] = n;
    }
}

// ---------------- K4: AVFE voxel-major (scales 0..2) + means for scale 3 ------
// one warp per voxel slot; lanes cover 2 channels each (c, c+32)
__global__ void __launch_bounds__(256) k_avfe(
    const float4* __restrict__ pts,
    const float* __restrict__ Wpt1,    // [4][64]
    const float* __restrict__ Watt1,   // [8][64]
    int N)
{
    __shared__ float sW1[256];
    __shared__ float sA1[512];
    int t = threadIdx.x;
    sW1[t] = Wpt1[t];
    sA1[t] = Watt1[t];
    sA1[t + 256] = Watt1[t + 256];
    __syncthreads();

    int gv = blockIdx.x * 8 + (t >> 5);
    int lane = t & 31;
    if (gv >= NVTOT) return;

    int s;
    if (gv < VB1) s = 0;
    else if (gv < VB2) s = 1;
    else if (gv < VB3) s = 2;
    else s = 3;

    int off = g_off[gv];
    int cnt = g_cnt[gv];
    const int* pix = &g_pidx[s * N + off];

    // ---- voxel mean ----
    float sx = 0.f, sy = 0.f, sz = 0.f, sw = 0.f;
    for (int j = lane; j < cnt; j += 32) {
        float4 p = pts[pix[j]];
        sx += p.x; sy += p.y; sz += p.z; sw += p.w;
    }
#pragma unroll
    for (int d = 16; d > 0; d >>= 1) {
        sx += __shfl_xor_sync(0xffffffffu, sx, d);
        sy += __shfl_xor_sync(0xffffffffu, sy, d);
        sz += __shfl_xor_sync(0xffffffffu, sz, d);
        sw += __shfl_xor_sync(0xffffffffu, sw, d);
    }
    float inv = 1.0f / fmaxf((float)cnt, 1.0f);
    float mx = sx * inv, my = sy * inv, mz = sz * inv, mw = sw * inv;

    if (s == 3) {
        if (lane == 0) {
            ((float4*)g_pmean3)[gv - VB3] = make_float4(mx, my, mz, mw);
        }
        return;
    }

    int cA = lane, cB = lane + 32;
    float mA = 0.f, mB = 0.f;
    for (int j = 0; j < cnt; j++) {
        int n = pix[j];             // broadcast load
        float4 p = pts[n];
        float a0 = p.x - mx, a1 = p.y - my, a2 = p.z - mz, a3 = p.w;
        float pfA = p.x * sW1[cA] + p.y * sW1[64 + cA] + p.z * sW1[128 + cA] + p.w * sW1[192 + cA];
        float pfB = p.x * sW1[cB] + p.y * sW1[64 + cB] + p.z * sW1[128 + cB] + p.w * sW1[192 + cB];
        pfA = fmaxf(pfA, 0.f); pfB = fmaxf(pfB, 0.f);
        float afA = a0 * sA1[cA] + a1 * sA1[64 + cA] + a2 * sA1[128 + cA] + a3 * sA1[192 + cA]
                  + mx * sA1[256 + cA] + my * sA1[320 + cA] + mz * sA1[384 + cA] + mw * sA1[448 + cA];
        float afB = a0 * sA1[cB] + a1 * sA1[64 + cB] + a2 * sA1[128 + cB] + a3 * sA1[192 + cB]
                  + mx * sA1[256 + cB] + my * sA1[320 + cB] + mz * sA1[384 + cB] + mw * sA1[448 + cB];
        afA = fmaxf(afA, 0.f); afB = fmaxf(afB, 0.f);
        float fA = pfA * afA, fB = pfB * afB;
        mA = fmaxf(mA, fA); mB = fmaxf(mB, fB);
        float* dst = &g_sfcat[(size_t)n * 192 + s * 64];
        dst[cA] = fA;
        dst[cB] = fB;
    }
    float* vdst = &g_vmax1[(size_t)gv * 64];
    vdst[cA] = mA;
    vdst[cB] = mB;
}

// ---------------- K5: U = vmax1 @ W_pt2[odd block], smem-tiled + f32x2 --------
// block = 128 threads (thread = output channel), 32 voxels per block
#define UMM_VT 32
#define UMM_T0 1875   // ceil(60000/32)
#define UMM_T1 938    // ceil(30000/32)
#define UMM_T2 469    // ceil(15000/32)
#define UMM_GRID (UMM_T0 + UMM_T1 + UMM_T2)
__global__ void __launch_bounds__(128) k_umm(const float* __restrict__ Wpt2) {
    __shared__ float At[64 * 36];    // [k][v] padded stride 36 (16B aligned rows)
    int b = blockIdx.x;
    int t = threadIdx.x;             // channel 0..127
    int s, gv0, vend;
    if (b < UMM_T0)                  { s = 0; gv0 = VB0 + b * UMM_VT;              vend = VB1; }
    else if (b < UMM_T0 + UMM_T1)    { s = 1; gv0 = VB1 + (b - UMM_T0) * UMM_VT;   vend = VB2; }
    else                             { s = 2; gv0 = VB2 + (b - UMM_T0 - UMM_T1) * UMM_VT; vend = VB3; }

    // stage A tile transposed: At[k*36 + v] = vmax1[gv0+v][k]
    for (int i = t; i < 512; i += 128) {      // 512 float4 chunks = 32 vox x 16
        int v = i >> 4, k4 = i & 15;
        int gv = gv0 + v;
        float4 f = (gv < vend) ? *(const float4*)&g_vmax1[(size_t)gv * 64 + k4 * 4]
                               : make_float4(0.f, 0.f, 0.f, 0.f);
        At[(k4 * 4 + 0) * 36 + v] = f.x;
        At[(k4 * 4 + 1) * 36 + v] = f.y;
        At[(k4 * 4 + 2) * 36 + v] = f.z;
        At[(k4 * 4 + 3) * 36 + v] = f.w;
    }
    __syncthreads();

    u64 acc[16];
#pragma unroll
    for (int i = 0; i < 16; i++) acc[i] = 0ull;

    const float* Wp = Wpt2 + (size_t)(128 * s + 64) * 128 + t;
#pragma unroll 4
    for (int k = 0; k < 64; k++) {
        float w = __ldg(Wp + (size_t)k * 128);
        u64 wd = pack2(w);
        const ulonglong2* row = (const ulonglong2*)&At[k * 36];
#pragma unroll
        for (int q = 0; q < 8; q++) {
            ulonglong2 a2 = row[q];             // voxels 4q..4q+3 as two f32x2
            fma2(acc[2 * q],     a2.x, wd);
            fma2(acc[2 * q + 1], a2.y, wd);
        }
    }

#pragma unroll
    for (int i = 0; i < 16; i++) {
        float2 f = unpack2(acc[i]);
        int gv = gv0 + 2 * i;
        if (gv < vend)     g_U[(size_t)gv * 128 + t] = f.x;
        if (gv + 1 < vend) g_U[(size_t)(gv + 1) * 128 + t] = f.y;
    }
}

// ---------------- K6a: big matvec + AVFEO attention, f32x2, 8 pts/warp --------
// block = 512 thr (16 warps), warp handles 8 points, lane handles 4 channels
#define AVFEO_SMEM ((24576 + 1024 + 16 * 8 * 192) * 4)   // 200704 B
__global__ void __launch_bounds__(512, 1) k_avfeo(
    const float4* __restrict__ pts,
    const float* __restrict__ Wpt2,    // [384][128]
    const float* __restrict__ Watt2,   // [8][128]
    const int* __restrict__ bev,
    int N)
{
    extern __shared__ float smem[];
    float* sWe = smem;                // [192][128] even (sf) blocks of W_pt2
    float* sA2 = smem + 24576;        // [8][128]
    float* sXS = smem + 24576 + 1024; // [16 warps][8 pts][192]
    int t = threadIdx.x;

    // stage even-block weights: sWe[s*64+k][c] = Wpt2[128s+k][c]
    for (int i = t; i < 6144; i += 512) {        // float4 granularity
        int idx = i * 4;
        int row = idx >> 7;
        int c = idx & 127;
        int grow = ((row >> 6) * 128) + (row & 63);
        ((float4*)sWe)[i] = *(const float4*)(Wpt2 + (size_t)grow * 128 + c);
    }
    for (int i = t; i < 1024; i += 512) sA2[i] = Watt2[i];
    __syncthreads();

    int w = t >> 5, lane = t & 31;
    float* xs = sXS + w * (8 * 192);
    const float4* U4 = (const float4*)g_U;
    const ulonglong2* We2 = (const ulonglong2*)sWe;
    const float4* A4 = (const float4*)sA2;
    int NG = (N + 127) >> 7;   // groups of 128 points per block iteration

    for (int g = blockIdx.x; g < NG; g += gridDim.x) {
        int nbase = g * 128 + w * 8;

        // stage x rows (8 points x 192 floats = 384 float4) into shared
#pragma unroll
        for (int r = 0; r < 12; r++) {
            int fid = lane + r * 32;             // 0..383 float4 slot
            int p = fid / 48, k4 = fid % 48;
            int n = nbase + p;
            float4 v = (n < N) ? ((const float4*)g_sfcat)[(size_t)n * 48 + k4]
                               : make_float4(0.f, 0.f, 0.f, 0.f);
            ((float4*)xs)[p * 48 + k4] = v;
        }
        __syncwarp();

        // init accumulators from U gathers (packed f32x2 pairs)
        u64 accl[8], acch[8];
        int i3[8];
#pragma unroll
        for (int p = 0; p < 8; p++) {
            int n = nbase + p;
            if (n < N) {
                int i0 = bev[n];
                int i1 = bev[N + n];
                int i2 = bev[2 * N + n];
                i3[p] = bev[3 * N + n];
                float4 a = U4[(size_t)i0 * 32 + lane];
                float4 b = U4[(size_t)(VB1 + i1) * 32 + lane];
                float4 c = U4[(size_t)(VB2 + i2) * 32 + lane];
                accl[p] = pack_pair(a.x + b.x + c.x, a.y + b.y + c.y);
                acch[p] = pack_pair(a.z + b.z + c.z, a.w + b.w + c.w);
            } else {
                i3[p] = 0;
                accl[p] = 0ull; acch[p] = 0ull;
            }
        }

        // main matvec: 192 x (8 pts x 4 ch), FFMA2
#pragma unroll 4
        for (int k = 0; k < 192; k += 2) {
            ulonglong2 wv0 = We2[k * 32 + lane];
            ulonglong2 wv1 = We2[(k + 1) * 32 + lane];
#pragma unroll
            for (int p = 0; p < 8; p++) {
                float2 x2 = *(const float2*)&xs[p * 192 + k];
                u64 xp0 = pack2(x2.x);
                u64 xp1 = pack2(x2.y);
                fma2(accl[p], xp0, wv0.x);
                fma2(acch[p], xp0, wv0.y);
                fma2(accl[p], xp1, wv1.x);
                fma2(acch[p], xp1, wv1.y);
            }
        }

        // epilogue: af2 attention, relu, product, store sf2
#pragma unroll
        for (int p = 0; p < 8; p++) {
            int n = nbase + p;
            if (n >= N) continue;
            float2 al = unpack2(accl[p]);
            float2 ah = unpack2(acch[p]);
            float4 pt = pts[n];
            float4 pm = ((const float4*)g_pmean3)[i3[p]];
            float att[8];
            att[0] = pt.x - pm.x; att[1] = pt.y - pm.y; att[2] = pt.z - pm.z; att[3] = pt.w;
            att[4] = pm.x; att[5] = pm.y; att[6] = pm.z; att[7] = pm.w;
            float4 af = make_float4(0.f, 0.f, 0.f, 0.f);
#pragma unroll
            for (int k = 0; k < 8; k++) {
                float4 wv = A4[k * 32 + lane];
                af.x = fmaf(att[k], wv.x, af.x);
                af.y = fmaf(att[k], wv.y, af.y);
                af.z = fmaf(att[k], wv.z, af.z);
                af.w = fmaf(att[k], wv.w, af.w);
            }
            float4 sf;
            sf.x = fmaxf(al.x, 0.f) * fmaxf(af.x, 0.f);
            sf.y = fmaxf(al.y, 0.f) * fmaxf(af.y, 0.f);
            sf.z = fmaxf(ah.x, 0.f) * fmaxf(af.z, 0.f);
            sf.w = fmaxf(ah.y, 0.f) * fmaxf(af.w, 0.f);
            ((float4*)g_sf2)[(size_t)n * 32 + lane] = sf;
        }
        __syncwarp();
    }
}

// ---------------- K6b: segment max over output voxels + fused scatter ---------
__global__ void k_vmax_scatter(const int* __restrict__ vfs,
                               float* __restrict__ out, int N) {
    int gw = (blockIdx.x * blockDim.x + threadIdx.x) >> 5;
    int lane = threadIdx.x & 31;
    if (gw >= NV3) return;
    int off = g_off[VB3 + gw];
    int cnt = g_cnt[VB3 + gw];
    const int* pix = &g_pidx[3 * N + off];
    float4 m = make_float4(0.f, 0.f, 0.f, 0.f);
    for (int j = 0; j < cnt; j++) {
        float4 v = ((const float4*)g_sf2)[(size_t)pix[j] * 32 + lane];
        m.x = fmaxf(m.x, v.x); m.y = fmaxf(m.y, v.y);
        m.z = fmaxf(m.z, v.z); m.w = fmaxf(m.w, v.w);
    }
    int b = vfs[gw * 3], y = vfs[gw * 3 + 1], x = vfs[gw * 3 + 2];
    int c0 = lane * 4;
    size_t base = ((size_t)b * CH_OUT + c0) * (HW * HW) + (size_t)y * HW + x;
    out[base]                = m.x;
    out[base + HW * HW]      = m.y;
    out[base + 2 * HW * HW]  = m.z;
    out[base + 3 * HW * HW]  = m.w;
}

// ---------------- launch ------------------------------------------------------
extern "C" void kernel_launch(void* const* d_in, const int* in_sizes, int n_in,
                              void* d_out, int out_size) {
    const float* pts   = (const float*)d_in[0];
    const float* Wpt1  = (const float*)d_in[1];
    const float* Watt1 = (const float*)d_in[2];
    const float* Wpt2  = (const float*)d_in[3];
    const float* Watt2 = (const float*)d_in[4];
    const int*   bev   = (const int*)d_in[5];
    const int*   vfs   = (const int*)d_in[6];
    float* out = (float*)d_out;
    int N = in_sizes[0] / 4;
    if (N > MAXN) N = MAXN;

    cudaMemsetAsync(d_out, 0, (size_t)out_size * sizeof(float), 0);
    k_zero_cnt<<<(NVTOT + 255) / 256, 256>>>();
    k_count<<<(N + 255) / 256, 256>>>(bev, N);
    k_scan<<<4, 1024>>>();
    k_fill<<<(N + 255) / 256, 256>>>(bev, N);
    k_avfe<<<(NVTOT + 7) / 8, 256>>>((const float4*)pts, Wpt1, Watt1, N);
    k_umm<<<UMM_GRID, 128>>>(Wpt2);
    cudaFuncSetAttribute(k_avfeo, cudaFuncAttributeMaxDynamicSharedMemorySize, AVFEO_SMEM);
    k_avfeo<<<148, 512, AVFEO_SMEM>>>((const float4*)pts, Wpt2, Watt2, bev, N);
    k_vmax_scatter<<<(NV3 * 32 + 255) / 256, 256>>>(vfs, out, N);
}

// round 9
// speedup vs baseline: 1.4547x; 1.1973x over previous
#include <cuda_runtime.h>

// ---------------- problem constants (fixed shapes for this problem) ----------
#define MAXN   300000
#define NV0    60000
#define NV1    30000
#define NV2    15000
#define NV3    120000
#define NVIN   105000     // NV0+NV1+NV2
#define NVTOT  225000     // + NV3
#define VB0    0
#define VB1    60000
#define VB2    90000
#define VB3    105000
#define CH_OUT 128
#define HW     512
#define NCELL  (2 * HW * HW)      // 524288

typedef unsigned long long u64;

// ---------------- packed f32x2 helpers (FFMA2 path, sm_103a) -----------------
__device__ __forceinline__ u64 pack2(float x) {
    u64 r; asm("mov.b64 %0, {%1, %1};" : "=l"(r) : "r"(__float_as_uint(x)));
    return r;
}
__device__ __forceinline__ void fma2(u64& d, u64 a, u64 b) {
    asm("fma.rn.f32x2 %0, %1, %2, %0;" : "+l"(d) : "l"(a), "l"(b));
}
__device__ __forceinline__ float2 unpack2(u64 v) {
    float2 f; asm("mov.b64 {%0, %1}, %2;" : "=f"(f.x), "=f"(f.y) : "l"(v));
    return f;
}

// ---------------- device scratch (static: no runtime allocation) -------------
__device__ int   g_cnt[NVTOT];
__device__ int   g_off[NVTOT];
__device__ int   g_cur[NVTOT];
__device__ int   g_pidx[4 * MAXN];
__device__ float g_sfcat[(size_t)MAXN * 192];   // [n][s*64+c] concatenated sf
__device__ float g_vmax1[(size_t)NVIN * 64];    // per input voxel max
__device__ float g_U[(size_t)NVIN * 128];       // vmax1 @ W_pt2_oddblock
__device__ float g_pmean3[NV3 * 4];             // output-scale voxel means
__device__ float g_sf2[(size_t)MAXN * 128];     // AVFEO per-point sf
__device__ float g_vmax2[(size_t)NV3 * 128];    // output-scale voxel max
__device__ int   g_inv[NCELL];                  // cell -> voxel id (-1 empty)

__constant__ int c_vbase[4] = {VB0, VB1, VB2, VB3};

// ---------------- K1: per-voxel counts (all 4 scales) -------------------------
__global__ void k_count(const int* __restrict__ bev, int N) {
    int n = blockIdx.x * blockDim.x + threadIdx.x;
    if (n >= N) return;
#pragma unroll
    for (int s = 0; s < 4; s++) {
        int v = bev[s * N + n];
        atomicAdd(&g_cnt[c_vbase[s] + v], 1);
    }
}

// ---------------- K2: exclusive scan per scale (one block per scale) ----------
__global__ void k_scan() {
    int s = blockIdx.x;
    int V = (s == 0) ? NV0 : (s == 1) ? NV1 : (s == 2) ? NV2 : NV3;
    int base = c_vbase[s];
    int t = threadIdx.x;
    int chunk = (V + 1023) >> 10;
    int st = t * chunk;
    int en = st + chunk; if (en > V) en = V;
    int sum = 0;
    for (int i = st; i < en; i++) sum += g_cnt[base + i];
    __shared__ int sh[1024];
    sh[t] = sum;
    __syncthreads();
    for (int d = 1; d < 1024; d <<= 1) {
        int v = (t >= d) ? sh[t - d] : 0;
        __syncthreads();
        sh[t] += v;
        __syncthreads();
    }
    int run = sh[t] - sum;   // exclusive prefix
    for (int i = st; i < en; i++) {
        int c = g_cnt[base + i];
        g_off[base + i] = run;
        g_cur[base + i] = run;
        run += c;
    }
}

// ---------------- K3: fill CSR point lists ------------------------------------
__global__ void k_fill(const int* __restrict__ bev, int N) {
    int n = blockIdx.x * blockDim.x + threadIdx.x;
    if (n >= N) return;
#pragma unroll
    for (int s = 0; s < 4; s++) {
        int v = bev[s * N + n];
        int pos = atomicAdd(&g_cur[c_vbase[s] + v], 1);
        g_pidx[s * N + pos] = n;
    }
}

// ---------------- K4: AVFE voxel-major (scales 0..2) + means for scale 3 ------
__global__ void __launch_bounds__(256) k_avfe(
    const float4* __restrict__ pts,
    const float* __restrict__ Wpt1,    // [4][64]
    const float* __restrict__ Watt1,   // [8][64]
    int N)
{
    __shared__ float sW1[256];
    __shared__ float sA1[512];
    int t = threadIdx.x;
    sW1[t] = Wpt1[t];
    sA1[t] = Watt1[t];
    sA1[t + 256] = Watt1[t + 256];
    __syncthreads();

    int gv = blockIdx.x * 8 + (t >> 5);
    int lane = t & 31;
    if (gv >= NVTOT) return;

    int s;
    if (gv < VB1) s = 0;
    else if (gv < VB2) s = 1;
    else if (gv < VB3) s = 2;
    else s = 3;

    int off = g_off[gv];
    int cnt = g_cnt[gv];
    const int* pix = &g_pidx[s * N + off];

    // ---- voxel mean ----
    float sx = 0.f, sy = 0.f, sz = 0.f, sw = 0.f;
    for (int j = lane; j < cnt; j += 32) {
        float4 p = pts[pix[j]];
        sx += p.x; sy += p.y; sz += p.z; sw += p.w;
    }
#pragma unroll
    for (int d = 16; d > 0; d >>= 1) {
        sx += __shfl_xor_sync(0xffffffffu, sx, d);
        sy += __shfl_xor_sync(0xffffffffu, sy, d);
        sz += __shfl_xor_sync(0xffffffffu, sz, d);
        sw += __shfl_xor_sync(0xffffffffu, sw, d);
    }
    float inv = 1.0f / fmaxf((float)cnt, 1.0f);
    float mx = sx * inv, my = sy * inv, mz = sz * inv, mw = sw * inv;

    if (s == 3) {
        if (lane == 0) {
            ((float4*)g_pmean3)[gv - VB3] = make_float4(mx, my, mz, mw);
        }
        return;
    }

    int cA = lane, cB = lane + 32;
    float mA = 0.f, mB = 0.f;
    for (int j = 0; j < cnt; j++) {
        int n = pix[j];             // broadcast load
        float4 p = pts[n];
        float a0 = p.x - mx, a1 = p.y - my, a2 = p.z - mz, a3 = p.w;
        float pfA = p.x * sW1[cA] + p.y * sW1[64 + cA] + p.z * sW1[128 + cA] + p.w * sW1[192 + cA];
        float pfB = p.x * sW1[cB] + p.y * sW1[64 + cB] + p.z * sW1[128 + cB] + p.w * sW1[192 + cB];
        pfA = fmaxf(pfA, 0.f); pfB = fmaxf(pfB, 0.f);
        float afA = a0 * sA1[cA] + a1 * sA1[64 + cA] + a2 * sA1[128 + cA] + a3 * sA1[192 + cA]
                  + mx * sA1[256 + cA] + my * sA1[320 + cA] + mz * sA1[384 + cA] + mw * sA1[448 + cA];
        float afB = a0 * sA1[cB] + a1 * sA1[64 + cB] + a2 * sA1[128 + cB] + a3 * sA1[192 + cB]
                  + mx * sA1[256 + cB] + my * sA1[320 + cB] + mz * sA1[384 + cB] + mw * sA1[448 + cB];
        afA = fmaxf(afA, 0.f); afB = fmaxf(afB, 0.f);
        float fA = pfA * afA, fB = pfB * afB;
        mA = fmaxf(mA, fA); mB = fmaxf(mB, fB);
        float* dst = &g_sfcat[(size_t)n * 192 + s * 64];
        dst[cA] = fA;
        dst[cB] = fB;
    }
    float* vdst = &g_vmax1[(size_t)gv * 64];
    vdst[cA] = mA;
    vdst[cB] = mB;
}

// ---------------- K5: U = vmax1 @ W_pt2[odd block], smem-tiled + f32x2 --------
#define UMM_VT 32
#define UMM_T0 1875   // ceil(60000/32)
#define UMM_T1 938    // ceil(30000/32)
#define UMM_T2 469    // ceil(15000/32)
#define UMM_GRID (UMM_T0 + UMM_T1 + UMM_T2)
__global__ void __launch_bounds__(128) k_umm(const float* __restrict__ Wpt2) {
    __shared__ float At[64 * 36];    // [k][v] padded stride 36
    int b = blockIdx.x;
    int t = threadIdx.x;             // channel 0..127
    int s, gv0, vend;
    if (b < UMM_T0)                  { s = 0; gv0 = VB0 + b * UMM_VT;              vend = VB1; }
    else if (b < UMM_T0 + UMM_T1)    { s = 1; gv0 = VB1 + (b - UMM_T0) * UMM_VT;   vend = VB2; }
    else                             { s = 2; gv0 = VB2 + (b - UMM_T0 - UMM_T1) * UMM_VT; vend = VB3; }

    for (int i = t; i < 512; i += 128) {
        int v = i >> 4, k4 = i & 15;
        int gv = gv0 + v;
        float4 f = (gv < vend) ? *(const float4*)&g_vmax1[(size_t)gv * 64 + k4 * 4]
                               : make_float4(0.f, 0.f, 0.f, 0.f);
        At[(k4 * 4 + 0) * 36 + v] = f.x;
        At[(k4 * 4 + 1) * 36 + v] = f.y;
        At[(k4 * 4 + 2) * 36 + v] = f.z;
        At[(k4 * 4 + 3) * 36 + v] = f.w;
    }
    __syncthreads();

    u64 acc[16];
#pragma unroll
    for (int i = 0; i < 16; i++) acc[i] = 0ull;

    const float* Wp = Wpt2 + (size_t)(128 * s + 64) * 128 + t;
#pragma unroll 4
    for (int k = 0; k < 64; k++) {
        float w = __ldg(Wp + (size_t)k * 128);
        u64 wd = pack2(w);
        const ulonglong2* row = (const ulonglong2*)&At[k * 36];
#pragma unroll
        for (int q = 0; q < 8; q++) {
            ulonglong2 a2 = row[q];
            fma2(acc[2 * q],     a2.x, wd);
            fma2(acc[2 * q + 1], a2.y, wd);
        }
    }

#pragma unroll
    for (int i = 0; i < 16; i++) {
        float2 f = unpack2(acc[i]);
        int gv = gv0 + 2 * i;
        if (gv < vend)     g_U[(size_t)gv * 128 + t] = f.x;
        if (gv + 1 < vend) g_U[(size_t)(gv + 1) * 128 + t] = f.y;
    }
}

// ---------------- K6a: big matvec + AVFEO attention -------------------------
// block = 512 thr (16 warps), warp handles 8 points, lane owns channels lane+32j
// FFMA2 paired over K: acc holds {even-k partial, odd-k partial}; both operands
// are natural LDS.64 (zero packing MOVs). Weights transposed, stride 97 u64.
#define WT_HS 97
// floats: sWt 128*194=24832, att 1024, xs 16*8*192=24576  -> 50432 floats
#define AVFEO_SMEM ((24832 + 1024 + 24576) * 4)
__global__ void __launch_bounds__(512, 1) k_avfeo(
    const float4* __restrict__ pts,
    const float* __restrict__ Wpt2,    // [384][128]
    const float* __restrict__ Watt2,   // [8][128]
    const int* __restrict__ bev,
    int N)
{
    extern __shared__ float smem[];
    float* sWt = smem;                 // transposed even-block weights [128][194]
    float* sA2 = smem + 24832;         // [8][128]
    float* sXS = smem + 24832 + 1024;  // [16 warps][8 pts][192]
    int t = threadIdx.x;

    // stage transposed weights: sWt[c*194 + kk] = Wpt2[grow(kk)][c]
    // grow(kk) = 128*(kk/64) + (kk%64)  (even = sf blocks)
    for (int i = t; i < 192 * 32; i += 512) {
        int kk = i >> 5, c4 = i & 31;
        int grow = ((kk >> 6) << 7) + (kk & 63);
        float4 f = *(const float4*)(Wpt2 + (size_t)grow * 128 + c4 * 4);
        float* base = sWt + (size_t)(c4 * 4) * (2 * WT_HS) + kk;
        base[0]            = f.x;
        base[2 * WT_HS]    = f.y;
        base[4 * WT_HS]    = f.z;
        base[6 * WT_HS]    = f.w;
    }
    for (int i = t; i < 1024; i += 512) sA2[i] = Watt2[i];
    __syncthreads();

    int w = t >> 5, lane = t & 31;
    float* xs = sXS + w * (8 * 192);
    const u64* xs64 = (const u64*)xs;
    const u64* Wt64 = (const u64*)sWt;     // channel c row at Wt64[c*97]
    int NG = (N + 127) >> 7;

    const u64* wrow0 = Wt64 + (size_t)(lane)       * WT_HS;
    const u64* wrow1 = Wt64 + (size_t)(lane + 32)  * WT_HS;
    const u64* wrow2 = Wt64 + (size_t)(lane + 64)  * WT_HS;
    const u64* wrow3 = Wt64 + (size_t)(lane + 96)  * WT_HS;

    for (int g = blockIdx.x; g < NG; g += gridDim.x) {
        int nbase = g * 128 + w * 8;

        // stage x rows (8 points x 192 floats = 384 float4) into shared
#pragma unroll
        for (int r = 0; r < 12; r++) {
            int fid = lane + r * 32;             // 0..383 float4 slot
            int p = fid / 48, k4 = fid % 48;
            int n = nbase + p;
            float4 v = (n < N) ? ((const float4*)g_sfcat)[(size_t)n * 48 + k4]
                               : make_float4(0.f, 0.f, 0.f, 0.f);
            ((float4*)xs)[p * 48 + k4] = v;
        }
        __syncwarp();

        u64 acc0[8], acc1[8], acc2[8], acc3[8];
#pragma unroll
        for (int p = 0; p < 8; p++) { acc0[p] = 0ull; acc1[p] = 0ull; acc2[p] = 0ull; acc3[p] = 0ull; }

        // main matvec: 96 k-pairs x (8 pts x 4 ch), all-natural LDS.64 operands
#pragma unroll 2
        for (int kh = 0; kh < 96; kh++) {
            u64 w0 = wrow0[kh];
            u64 w1 = wrow1[kh];
            u64 w2 = wrow2[kh];
            u64 w3 = wrow3[kh];
#pragma unroll
            for (int p = 0; p < 8; p++) {
                u64 xp = xs64[p * 96 + kh];
                fma2(acc0[p], xp, w0);
                fma2(acc1[p], xp, w1);
                fma2(acc2[p], xp, w2);
                fma2(acc3[p], xp, w3);
            }
        }

        // epilogue
#pragma unroll
        for (int p = 0; p < 8; p++) {
            int n = nbase + p;
            if (n >= N) continue;
            float2 h0 = unpack2(acc0[p]);
            float2 h1 = unpack2(acc1[p]);
            float2 h2 = unpack2(acc2[p]);
            float2 h3 = unpack2(acc3[p]);
            float s0 = h0.x + h0.y, s1 = h1.x + h1.y;
            float s2 = h2.x + h2.y, s3 = h3.x + h3.y;

            int i0 = bev[n];
            int i1 = bev[N + n];
            int i2 = bev[2 * N + n];
            int i3 = bev[3 * N + n];
            const float* u0r = &g_U[(size_t)i0 * 128];
            const float* u1r = &g_U[(size_t)(VB1 + i1) * 128];
            const float* u2r = &g_U[(size_t)(VB2 + i2) * 128];
            s0 += u0r[lane]      + u1r[lane]      + u2r[lane];
            s1 += u0r[lane + 32] + u1r[lane + 32] + u2r[lane + 32];
            s2 += u0r[lane + 64] + u1r[lane + 64] + u2r[lane + 64];
            s3 += u0r[lane + 96] + u1r[lane + 96] + u2r[lane + 96];

            float4 pt = pts[n];
            float4 pm = ((const float4*)g_pmean3)[i3];
            float att[8];
            att[0] = pt.x - pm.x; att[1] = pt.y - pm.y; att[2] = pt.z - pm.z; att[3] = pt.w;
            att[4] = pm.x; att[5] = pm.y; att[6] = pm.z; att[7] = pm.w;
            float af0 = 0.f, af1 = 0.f, af2 = 0.f, af3 = 0.f;
#pragma unroll
            for (int k = 0; k < 8; k++) {
                const float* ar = &sA2[k * 128];
                af0 = fmaf(att[k], ar[lane],      af0);
                af1 = fmaf(att[k], ar[lane + 32], af1);
                af2 = fmaf(att[k], ar[lane + 64], af2);
                af3 = fmaf(att[k], ar[lane + 96], af3);
            }
            float* orow = &g_sf2[(size_t)n * 128];
            orow[lane]      = fmaxf(s0, 0.f) * fmaxf(af0, 0.f);
            orow[lane + 32] = fmaxf(s1, 0.f) * fmaxf(af1, 0.f);
            orow[lane + 64] = fmaxf(s2, 0.f) * fmaxf(af2, 0.f);
            orow[lane + 96] = fmaxf(s3, 0.f) * fmaxf(af3, 0.f);
        }
        __syncwarp();
    }
}

// ---------------- K6b: segment max over output voxels (coalesced store) ------
__global__ void k_vmax2(int N) {
    int gw = (blockIdx.x * blockDim.x + threadIdx.x) >> 5;
    int lane = threadIdx.x & 31;
    if (gw >= NV3) return;
    int off = g_off[VB3 + gw];
    int cnt = g_cnt[VB3 + gw];
    const int* pix = &g_pidx[3 * N + off];
    float4 m = make_float4(0.f, 0.f, 0.f, 0.f);
    for (int j = 0; j < cnt; j++) {
        float4 v = ((const float4*)g_sf2)[(size_t)pix[j] * 32 + lane];
        m.x = fmaxf(m.x, v.x); m.y = fmaxf(m.y, v.y);
        m.z = fmaxf(m.z, v.z); m.w = fmaxf(m.w, v.w);
    }
    ((float4*)g_vmax2)[(size_t)gw * 32 + lane] = m;
}

// ---------------- K7a: fill inverse cell->voxel map ---------------------------
__global__ void k_invfill(const int* __restrict__ vfs) {
    int o = blockIdx.x * blockDim.x + threadIdx.x;
    if (o >= NV3) return;
    int b = vfs[o * 3], y = vfs[o * 3 + 1], x = vfs[o * 3 + 2];
    g_inv[(b << 18) + (y << 9) + x] = o;
}

// ---------------- K7b: dense coalesced output writer --------------------------
// one block per (b, y) row; writes ALL 128*512 floats of that row (zeros incl.)
#define DENSE_CAP 192
#define DENSE_SMEM (512 * 4 + DENSE_CAP * 4 + DENSE_CAP * 132 * 4 + 16)
__global__ void __launch_bounds__(256) k_dense(float* __restrict__ out) {
    extern __shared__ char dsm[];
    int*   s_inv  = (int*)dsm;                         // 512
    int*   s_vox  = (int*)(dsm + 2048);                // DENSE_CAP
    float* s_vals = (float*)(dsm + 2048 + DENSE_CAP * 4);
    __shared__ int s_cnt;
    int t = threadIdx.x;
    int by = blockIdx.x;
    int b = by >> 9, y = by & 511;
    const int* invrow = g_inv + (size_t)by * 512;

    if (t == 0) s_cnt = 0;
    __syncthreads();
    for (int x = t; x < 512; x += 256) {
        int v = invrow[x];
        int tag = -1;
        if (v >= 0) {
            int slot = atomicAdd(&s_cnt, 1);
            if (slot < DENSE_CAP) { s_vox[slot] = v; tag = slot; }
            else tag = -2 - v;            // direct-gmem fallback
        }
        s_inv[x] = tag;
    }
    __syncthreads();
    int cnt = s_cnt; if (cnt > DENSE_CAP) cnt = DENSE_CAP;

    // stage occupied voxel rows (coalesced reads of vmax2)
    for (int i = t; i < cnt * 128; i += 256) {
        int slot = i >> 7, c = i & 127;
        s_vals[slot * 132 + c] = g_vmax2[(size_t)s_vox[slot] * 128 + c];
    }
    __syncthreads();

    size_t rowbase = (size_t)b * CH_OUT * (HW * HW) + (size_t)y * HW;
#pragma unroll 4
    for (int it = 0; it < 64; it++) {
        int idx = it * 256 + t;
        int c = idx >> 7, x4 = idx & 127;
        float4 o;
        float vals[4];
#pragma unroll
        for (int gg = 0; gg < 4; gg++) {
            int x = x4 * 4 + gg;
            int sl = s_inv[x];
            float v = 0.f;
            if (sl >= 0) v = s_vals[sl * 132 + c];
            else if (sl != -1) v = g_vmax2[(size_t)(-2 - sl) * 128 + c];
            vals[gg] = v;
        }
        o.x = vals[0]; o.y = vals[1]; o.z = vals[2]; o.w = vals[3];
        ((float4*)(out + rowbase + (size_t)c * (HW * HW)))[x4] = o;
    }
}

// ---------------- launch ------------------------------------------------------
extern "C" void kernel_launch(void* const* d_in, const int* in_sizes, int n_in,
                              void* d_out, int out_size) {
    const float* pts   = (const float*)d_in[0];
    const float* Wpt1  = (const float*)d_in[1];
    const float* Watt1 = (const float*)d_in[2];
    const float* Wpt2  = (const float*)d_in[3];
    const float* Watt2 = (const float*)d_in[4];
    const int*   bev   = (const int*)d_in[5];
    const int*   vfs   = (const int*)d_in[6];
    float* out = (float*)d_out;
    int N = in_sizes[0] / 4;
    if (N > MAXN) N = MAXN;

    void *p_cnt = 0, *p_inv = 0;
    cudaGetSymbolAddress(&p_cnt, g_cnt);
    cudaGetSymbolAddress(&p_inv, g_inv);
    cudaMemsetAsync(p_cnt, 0, NVTOT * sizeof(int), 0);
    cudaMemsetAsync(p_inv, 0xFF, NCELL * sizeof(int), 0);   // -1 everywhere

    k_count<<<(N + 255) / 256, 256>>>(bev, N);
    k_scan<<<4, 1024>>>();
    k_fill<<<(N + 255) / 256, 256>>>(bev, N);
    k_avfe<<<(NVTOT + 7) / 8, 256>>>((const float4*)pts, Wpt1, Watt1, N);
    k_umm<<<UMM_GRID, 128>>>(Wpt2);
    cudaFuncSetAttribute(k_avfeo, cudaFuncAttributeMaxDynamicSharedMemorySize, AVFEO_SMEM);
    k_avfeo<<<148, 512, AVFEO_SMEM>>>((const float4*)pts, Wpt2, Watt2, bev, N);
    k_invfill<<<(NV3 + 255) / 256, 256>>>(vfs);
    k_vmax2<<<(NV3 * 32 + 255) / 256, 256>>>(N);
    cudaFuncSetAttribute(k_dense, cudaFuncAttributeMaxDynamicSharedMemorySize, DENSE_SMEM);
    k_dense<<<2 * HW, 256, DENSE_SMEM>>>(out);
}

// round 11
// speedup vs baseline: 1.5259x; 1.0490x over previous
#include <cuda_runtime.h>

// ---------------- problem constants (fixed shapes for this problem) ----------
#define MAXN   300000
#define NV0    60000
#define NV1    30000
#define NV2    15000
#define NV3    120000
#define NVIN   105000     // NV0+NV1+NV2
#define NVTOT  225000     // + NV3
#define VB0    0
#define VB1    60000
#define VB2    90000
#define VB3    105000
#define CH_OUT 128
#define HW     512
#define NCELL  (2 * HW * HW)      // 524288

typedef unsigned long long u64;

// ---------------- packed f32x2 helpers (FFMA2 path, sm_103a) -----------------
__device__ __forceinline__ u64 pack2(float x) {
    u64 r; asm("mov.b64 %0, {%1, %1};" : "=l"(r) : "r"(__float_as_uint(x)));
    return r;
}
__device__ __forceinline__ void fma2(u64& d, u64 a, u64 b) {
    asm("fma.rn.f32x2 %0, %1, %2, %0;" : "+l"(d) : "l"(a), "l"(b));
}
__device__ __forceinline__ float2 unpack2(u64 v) {
    float2 f; asm("mov.b64 {%0, %1}, %2;" : "=f"(f.x), "=f"(f.y) : "l"(v));
    return f;
}

// ---------------- device scratch (static: no runtime allocation) -------------
__device__ int   g_cnt[NVTOT];
__device__ int   g_off[NVTOT];
__device__ int   g_cur[NVTOT];
__device__ int   g_pidx[4 * MAXN];
__device__ float g_sfcat[(size_t)MAXN * 192];   // [n][s*64+c] concatenated sf
__device__ float g_vmax1[(size_t)NVIN * 64];    // per input voxel max
__device__ float g_U[(size_t)NVIN * 128];       // vmax1 @ W_pt2_oddblock
__device__ float g_pmean3[NV3 * 4];             // output-scale voxel means
__device__ float g_vmax2[(size_t)NV3 * 128];    // output voxel max (atomicMax)
__device__ int   g_inv[NCELL];                  // cell -> voxel id (-1 empty)

__constant__ int c_vbase[4] = {VB0, VB1, VB2, VB3};

// ---------------- K1: per-voxel counts (all 4 scales) -------------------------
__global__ void k_count(const int* __restrict__ bev, int N) {
    int n = blockIdx.x * blockDim.x + threadIdx.x;
    if (n >= N) return;
#pragma unroll
    for (int s = 0; s < 4; s++) {
        int v = bev[s * N + n];
        atomicAdd(&g_cnt[c_vbase[s] + v], 1);
    }
}

// ---------------- K2: exclusive scan per scale (one block per scale) ----------
__global__ void k_scan() {
    int s = blockIdx.x;
    int V = (s == 0) ? NV0 : (s == 1) ? NV1 : (s == 2) ? NV2 : NV3;
    int base = c_vbase[s];
    int t = threadIdx.x;
    int chunk = (V + 1023) >> 10;
    int st = t * chunk;
    int en = st + chunk; if (en > V) en = V;
    int sum = 0;
    for (int i = st; i < en; i++) sum += g_cnt[base + i];
    __shared__ int sh[1024];
    sh[t] = sum;
    __syncthreads();
    for (int d = 1; d < 1024; d <<= 1) {
        int v = (t >= d) ? sh[t - d] : 0;
        __syncthreads();
        sh[t] += v;
        __syncthreads();
    }
    int run = sh[t] - sum;   // exclusive prefix
    for (int i = st; i < en; i++) {
        int c = g_cnt[base + i];
        g_off[base + i] = run;
        g_cur[base + i] = run;
        run += c;
    }
}

// ---------------- K3: fill CSR point lists ------------------------------------
__global__ void k_fill(const int* __restrict__ bev, int N) {
    int n = blockIdx.x * blockDim.x + threadIdx.x;
    if (n >= N) return;
#pragma unroll
    for (int s = 0; s < 4; s++) {
        int v = bev[s * N + n];
        int pos = atomicAdd(&g_cur[c_vbase[s] + v], 1);
        g_pidx[s * N + pos] = n;
    }
}

// ---------------- K4: AVFE voxel-major (scales 0..2) + means for scale 3 ------
// one warp per voxel; lanes cover channels (lane, lane+32); software-pipelined
__global__ void __launch_bounds__(256) k_avfe(
    const float4* __restrict__ pts,
    const float* __restrict__ Wpt1,    // [4][64]
    const float* __restrict__ Watt1,   // [8][64]
    int N)
{
    __shared__ float sW1[256];
    __shared__ float sA1[512];
    int t = threadIdx.x;
    sW1[t] = Wpt1[t];
    sA1[t] = Watt1[t];
    sA1[t + 256] = Watt1[t + 256];
    __syncthreads();

    int gv = blockIdx.x * 8 + (t >> 5);
    int lane = t & 31;
    if (gv >= NVTOT) return;

    int s;
    if (gv < VB1) s = 0;
    else if (gv < VB2) s = 1;
    else if (gv < VB3) s = 2;
    else s = 3;

    int off = g_off[gv];
    int cnt = g_cnt[gv];
    const int* pix = &g_pidx[s * N + off];

    // ---- voxel mean ----
    float sx = 0.f, sy = 0.f, sz = 0.f, sw = 0.f;
    for (int j = lane; j < cnt; j += 32) {
        float4 p = pts[pix[j]];
        sx += p.x; sy += p.y; sz += p.z; sw += p.w;
    }
#pragma unroll
    for (int d = 16; d > 0; d >>= 1) {
        sx += __shfl_xor_sync(0xffffffffu, sx, d);
        sy += __shfl_xor_sync(0xffffffffu, sy, d);
        sz += __shfl_xor_sync(0xffffffffu, sz, d);
        sw += __shfl_xor_sync(0xffffffffu, sw, d);
    }
    float inv = 1.0f / fmaxf((float)cnt, 1.0f);
    float mx = sx * inv, my = sy * inv, mz = sz * inv, mw = sw * inv;

    if (s == 3) {
        if (lane == 0) {
            ((float4*)g_pmean3)[gv - VB3] = make_float4(mx, my, mz, mw);
        }
        return;
    }
    if (cnt <= 0) return;

    int cA = lane, cB = lane + 32;
    // hoist loop-invariant weight reads into registers
    float w0A = sW1[cA],       w1A = sW1[64 + cA],  w2A = sW1[128 + cA], w3A = sW1[192 + cA];
    float w0B = sW1[cB],       w1B = sW1[64 + cB],  w2B = sW1[128 + cB], w3B = sW1[192 + cB];
    float a0A = sA1[cA],       a1A = sA1[64 + cA],  a2A = sA1[128 + cA], a3A = sA1[192 + cA];
    float a4A = sA1[256 + cA], a5A = sA1[320 + cA], a6A = sA1[384 + cA], a7A = sA1[448 + cA];
    float a0B = sA1[cB],       a1B = sA1[64 + cB],  a2B = sA1[128 + cB], a3B = sA1[192 + cB];
    float a4B = sA1[256 + cB], a5B = sA1[320 + cB], a6B = sA1[384 + cB], a7B = sA1[448 + cB];
    // attention mean part is loop-invariant
    float mtA = mx * a4A + my * a5A + mz * a6A + mw * a7A;
    float mtB = mx * a4B + my * a5B + mz * a6B + mw * a7B;

    float mA = 0.f, mB = 0.f;
    int n_cur = pix[0];
    float4 p_cur = pts[n_cur];
    for (int j = 0; j < cnt; j++) {
        int n = n_cur;
        float4 p = p_cur;
        if (j + 1 < cnt) {                 // prefetch next point
            n_cur = pix[j + 1];
            p_cur = pts[n_cur];
        }
        float d0 = p.x - mx, d1 = p.y - my, d2 = p.z - mz;
        float pfA = fmaxf(p.x * w0A + p.y * w1A + p.z * w2A + p.w * w3A, 0.f);
        float pfB = fmaxf(p.x * w0B + p.y * w1B + p.z * w2B + p.w * w3B, 0.f);
        float afA = fmaxf(d0 * a0A + d1 * a1A + d2 * a2A + p.w * a3A + mtA, 0.f);
        float afB = fmaxf(d0 * a0B + d1 * a1B + d2 * a2B + p.w * a3B + mtB, 0.f);
        float fA = pfA * afA, fB = pfB * afB;
        mA = fmaxf(mA, fA); mB = fmaxf(mB, fB);
        float* dst = &g_sfcat[(size_t)n * 192 + s * 64];
        dst[cA] = fA;
        dst[cB] = fB;
    }
    float* vdst = &g_vmax1[(size_t)gv * 64];
    vdst[cA] = mA;
    vdst[cB] = mB;
}

// ---------------- K5: U = vmax1 @ W_pt2[odd block], smem-tiled + f32x2 --------
#define UMM_VT 32
#define UMM_T0 1875   // ceil(60000/32)
#define UMM_T1 938    // ceil(30000/32)
#define UMM_T2 469    // ceil(15000/32)
#define UMM_GRID (UMM_T0 + UMM_T1 + UMM_T2)
__global__ void __launch_bounds__(128) k_umm(const float* __restrict__ Wpt2) {
    __shared__ float At[64 * 36];    // [k][v] padded stride 36
    int b = blockIdx.x;
    int t = threadIdx.x;             // channel 0..127
    int s, gv0, vend;
    if (b < UMM_T0)                  { s = 0; gv0 = VB0 + b * UMM_VT;              vend = VB1; }
    else if (b < UMM_T0 + UMM_T1)    { s = 1; gv0 = VB1 + (b - UMM_T0) * UMM_VT;   vend = VB2; }
    else                             { s = 2; gv0 = VB2 + (b - UMM_T0 - UMM_T1) * UMM_VT; vend = VB3; }

    for (int i = t; i < 512; i += 128) {
        int v = i >> 4, k4 = i & 15;
        int gv = gv0 + v;
        float4 f = (gv < vend) ? *(const float4*)&g_vmax1[(size_t)gv * 64 + k4 * 4]
                               : make_float4(0.f, 0.f, 0.f, 0.f);
        At[(k4 * 4 + 0) * 36 + v] = f.x;
        At[(k4 * 4 + 1) * 36 + v] = f.y;
        At[(k4 * 4 + 2) * 36 + v] = f.z;
        At[(k4 * 4 + 3) * 36 + v] = f.w;
    }
    __syncthreads();

    u64 acc[16];
#pragma unroll
    for (int i = 0; i < 16; i++) acc[i] = 0ull;

    const float* Wp = Wpt2 + (size_t)(128 * s + 64) * 128 + t;
#pragma unroll 4
    for (int k = 0; k < 64; k++) {
        float w = __ldg(Wp + (size_t)k * 128);
        u64 wd = pack2(w);
        const ulonglong2* row = (const ulonglong2*)&At[k * 36];
#pragma unroll
        for (int q = 0; q < 8; q++) {
            ulonglong2 a2 = row[q];
            fma2(acc[2 * q],     a2.x, wd);
            fma2(acc[2 * q + 1], a2.y, wd);
        }
    }

#pragma unroll
    for (int i = 0; i < 16; i++) {
        float2 f = unpack2(acc[i]);
        int gv = gv0 + 2 * i;
        if (gv < vend)     g_U[(size_t)gv * 128 + t] = f.x;
        if (gv + 1 < vend) g_U[(size_t)(gv + 1) * 128 + t] = f.y;
    }
}

// ---------------- K6: big matvec + AVFEO attention + fused atomic segmax ------
// block = 512 thr (16 warps), warp handles 8 points, lane owns channels lane+32j
// FFMA2 paired over K; weights transposed stride-97-u64 (conflict-free LDS.64).
// Epilogue: sf2 values are relu*relu >= 0  ->  int-bitwise atomicMax into
// g_vmax2 is exact & order-independent; kills the sf2 store+reload round trip.
#define WT_HS 97
#define AVFEO_SMEM ((24832 + 1024 + 24576) * 4)
__global__ void __launch_bounds__(512, 1) k_avfeo(
    const float4* __restrict__ pts,
    const float* __restrict__ Wpt2,    // [384][128]
    const float* __restrict__ Watt2,   // [8][128]
    const int* __restrict__ bev,
    int N)
{
    extern __shared__ float smem[];
    float* sWt = smem;                 // transposed even-block weights [128][194]
    float* sA2 = smem + 24832;         // [8][128]
    float* sXS = smem + 24832 + 1024;  // [16 warps][8 pts][192]
    int t = threadIdx.x;

    for (int i = t; i < 192 * 32; i += 512) {
        int kk = i >> 5, c4 = i & 31;
        int grow = ((kk >> 6) << 7) + (kk & 63);
        float4 f = *(const float4*)(Wpt2 + (size_t)grow * 128 + c4 * 4);
        float* base = sWt + (size_t)(c4 * 4) * (2 * WT_HS) + kk;
        base[0]            = f.x;
        base[2 * WT_HS]    = f.y;
        base[4 * WT_HS]    = f.z;
        base[6 * WT_HS]    = f.w;
    }
    for (int i = t; i < 1024; i += 512) sA2[i] = Watt2[i];
    __syncthreads();

    int w = t >> 5, lane = t & 31;
    float* xs = sXS + w * (8 * 192);
    const u64* xs64 = (const u64*)xs;
    const u64* Wt64 = (const u64*)sWt;
    int NG = (N + 127) >> 7;

    const u64* wrow0 = Wt64 + (size_t)(lane)       * WT_HS;
    const u64* wrow1 = Wt64 + (size_t)(lane + 32)  * WT_HS;
    const u64* wrow2 = Wt64 + (size_t)(lane + 64)  * WT_HS;
    const u64* wrow3 = Wt64 + (size_t)(lane + 96)  * WT_HS;

    for (int g = blockIdx.x; g < NG; g += gridDim.x) {
        int nbase = g * 128 + w * 8;

#pragma unroll
        for (int r = 0; r < 12; r++) {
            int fid = lane + r * 32;
            int p = fid / 48, k4 = fid % 48;
            int n = nbase + p;
            float4 v = (n < N) ? ((const float4*)g_sfcat)[(size_t)n * 48 + k4]
                               : make_float4(0.f, 0.f, 0.f, 0.f);
            ((float4*)xs)[p * 48 + k4] = v;
        }
        __syncwarp();

        u64 acc0[8], acc1[8], acc2[8], acc3[8];
#pragma unroll
        for (int p = 0; p < 8; p++) { acc0[p] = 0ull; acc1[p] = 0ull; acc2[p] = 0ull; acc3[p] = 0ull; }

#pragma unroll 2
        for (int kh = 0; kh < 96; kh++) {
            u64 w0 = wrow0[kh];
            u64 w1 = wrow1[kh];
            u64 w2 = wrow2[kh];
            u64 w3 = wrow3[kh];
#pragma unroll
            for (int p = 0; p < 8; p++) {
                u64 xp = xs64[p * 96 + kh];
                fma2(acc0[p], xp, w0);
                fma2(acc1[p], xp, w1);
                fma2(acc2[p], xp, w2);
                fma2(acc3[p], xp, w3);
            }
        }

#pragma unroll
        for (int p = 0; p < 8; p++) {
            int n = nbase + p;
            if (n >= N) continue;
            float2 h0 = unpack2(acc0[p]);
            float2 h1 = unpack2(acc1[p]);
            float2 h2 = unpack2(acc2[p]);
            float2 h3 = unpack2(acc3[p]);
            float s0 = h0.x + h0.y, s1 = h1.x + h1.y;
            float s2 = h2.x + h2.y, s3 = h3.x + h3.y;

            int i0 = bev[n];
            int i1 = bev[N + n];
            int i2 = bev[2 * N + n];
            int i3 = bev[3 * N + n];
            const float* u0r = &g_U[(size_t)i0 * 128];
            const float* u1r = &g_U[(size_t)(VB1 + i1) * 128];
            const float* u2r = &g_U[(size_t)(VB2 + i2) * 128];
            s0 += u0r[lane]      + u1r[lane]      + u2r[lane];
            s1 += u0r[lane + 32] + u1r[lane + 32] + u2r[lane + 32];
            s2 += u0r[lane + 64] + u1r[lane + 64] + u2r[lane + 64];
            s3 += u0r[lane + 96] + u1r[lane + 96] + u2r[lane + 96];

            float4 pt = pts[n];
            float4 pm = ((const float4*)g_pmean3)[i3];
            float att[8];
            att[0] = pt.x - pm.x; att[1] = pt.y - pm.y; att[2] = pt.z - pm.z; att[3] = pt.w;
            att[4] = pm.x; att[5] = pm.y; att[6] = pm.z; att[7] = pm.w;
            float af0 = 0.f, af1 = 0.f, af2 = 0.f, af3 = 0.f;
#pragma unroll
            for (int k = 0; k < 8; k++) {
                const float* ar = &sA2[k * 128];
                af0 = fmaf(att[k], ar[lane],      af0);
                af1 = fmaf(att[k], ar[lane + 32], af1);
                af2 = fmaf(att[k], ar[lane + 64], af2);
                af3 = fmaf(att[k], ar[lane + 96], af3);
            }
            float v0 = fmaxf(s0, 0.f) * fmaxf(af0, 0.f);
            float v1 = fmaxf(s1, 0.f) * fmaxf(af1, 0.f);
            float v2 = fmaxf(s2, 0.f) * fmaxf(af2, 0.f);
            float v3 = fmaxf(s3, 0.f) * fmaxf(af3, 0.f);
            // fused segment-max: values >= 0 so int-bit max == float max
            int* vrow = (int*)&g_vmax2[(size_t)i3 * 128];
            atomicMax(&vrow[lane],      __float_as_int(v0));
            atomicMax(&vrow[lane + 32], __float_as_int(v1));
            atomicMax(&vrow[lane + 64], __float_as_int(v2));
            atomicMax(&vrow[lane + 96], __float_as_int(v3));
        }
        __syncwarp();
    }
}

// ---------------- K7a: fill inverse cell->voxel map ---------------------------
__global__ void k_invfill(const int* __restrict__ vfs) {
    int o = blockIdx.x * blockDim.x + threadIdx.x;
    if (o >= NV3) return;
    int b = vfs[o * 3], y = vfs[o * 3 + 1], x = vfs[o * 3 + 2];
    g_inv[(b << 18) + (y << 9) + x] = o;
}

// ---------------- K7b: dense coalesced output writer --------------------------
#define DENSE_CAP 192
#define DENSE_SMEM (512 * 4 + DENSE_CAP * 4 + DENSE_CAP * 132 * 4 + 16)
__global__ void __launch_bounds__(256) k_dense(float* __restrict__ out) {
    extern __shared__ char dsm[];
    int*   s_inv  = (int*)dsm;                         // 512
    int*   s_vox  = (int*)(dsm + 2048);                // DENSE_CAP
    float* s_vals = (float*)(dsm + 2048 + DENSE_CAP * 4);
    __shared__ int s_cnt;
    int t = threadIdx.x;
    int by = blockIdx.x;
    int b = by >> 9, y = by & 511;
    const int* invrow = g_inv + (size_t)by * 512;

    if (t == 0) s_cnt = 0;
    __syncthreads();
    for (int x = t; x < 512; x += 256) {
        int v = invrow[x];
        int tag = -1;
        if (v >= 0) {
            int slot = atomicAdd(&s_cnt, 1);
            if (slot < DENSE_CAP) { s_vox[slot] = v; tag = slot; }
            else tag = -2 - v;            // direct-gmem fallback
        }
        s_inv[x] = tag;
    }
    __syncthreads();
    int cnt = s_cnt; if (cnt > DENSE_CAP) cnt = DENSE_CAP;

    for (int i = t; i < cnt * 128; i += 256) {
        int slot = i >> 7, c = i & 127;
        s_vals[slot * 132 + c] = g_vmax2[(size_t)s_vox[slot] * 128 + c];
    }
    __syncthreads();

    size_t rowbase = (size_t)b * CH_OUT * (HW * HW) + (size_t)y * HW;
#pragma unroll 4
    for (int it = 0; it < 64; it++) {
        int idx = it * 256 + t;
        int c = idx >> 7, x4 = idx & 127;
        float4 o;
        float vals[4];
#pragma unroll
        for (int gg = 0; gg < 4; gg++) {
            int x = x4 * 4 + gg;
            int sl = s_inv[x];
            float v = 0.f;
            if (sl >= 0) v = s_vals[sl * 132 + c];
            else if (sl != -1) v = g_vmax2[(size_t)(-2 - sl) * 128 + c];
            vals[gg] = v;
        }
        o.x = vals[0]; o.y = vals[1]; o.z = vals[2]; o.w = vals[3];
        ((float4*)(out + rowbase + (size_t)c * (HW * HW)))[x4] = o;
    }
}

// ---------------- launch ------------------------------------------------------
extern "C" void kernel_launch(void* const* d_in, const int* in_sizes, int n_in,
                              void* d_out, int out_size) {
    const float* pts   = (const float*)d_in[0];
    const float* Wpt1  = (const float*)d_in[1];
    const float* Watt1 = (const float*)d_in[2];
    const float* Wpt2  = (const float*)d_in[3];
    const float* Watt2 = (const float*)d_in[4];
    const int*   bev   = (const int*)d_in[5];
    const int*   vfs   = (const int*)d_in[6];
    float* out = (float*)d_out;
    int N = in_sizes[0] / 4;
    if (N > MAXN) N = MAXN;

    void *p_cnt = 0, *p_inv = 0, *p_vm2 = 0;
    cudaGetSymbolAddress(&p_cnt, g_cnt);
    cudaGetSymbolAddress(&p_inv, g_inv);
    cudaGetSymbolAddress(&p_vm2, g_vmax2);
    cudaMemsetAsync(p_cnt, 0, NVTOT * sizeof(int), 0);
    cudaMemsetAsync(p_inv, 0xFF, NCELL * sizeof(int), 0);       // -1 everywhere
    cudaMemsetAsync(p_vm2, 0, (size_t)NV3 * 128 * sizeof(float), 0);  // 0.0f identity

    k_count<<<(N + 255) / 256, 256>>>(bev, N);
    k_scan<<<4, 1024>>>();
    k_fill<<<(N + 255) / 256, 256>>>(bev, N);
    k_avfe<<<(NVTOT + 7) / 8, 256>>>((const float4*)pts, Wpt1, Watt1, N);
    k_umm<<<UMM_GRID, 128>>>(Wpt2);
    cudaFuncSetAttribute(k_avfeo, cudaFuncAttributeMaxDynamicSharedMemorySize, AVFEO_SMEM);
    k_avfeo<<<148, 512, AVFEO_SMEM>>>((const float4*)pts, Wpt2, Watt2, bev, N);
    k_invfill<<<(NV3 + 255) / 256, 256>>>(vfs);
    cudaFuncSetAttribute(k_dense, cudaFuncAttributeMaxDynamicSharedMemorySize, DENSE_SMEM);
    k_dense<<<2 * HW, 256, DENSE_SMEM>>>(out);
}